// round 16
// baseline (speedup 1.0000x reference)
#include <cuda_runtime.h>
#include <stdint.h>

#define B_   4096
#define F_   1024
#define H_   256
#define C_   10
#define T_   24
#define T2   (T_ - 2)     // steps 22/23 gathers are dead
#define RPB  4
#define EMAX 512          // max spiking encoder elements per row (mean ~141)

// ---- transposed weights (device globals; no allocation) ----
__device__ __align__(16) float g_W1T[F_ * H_];   // [f][j]
__device__ __align__(16) float g_W2T[H_ * H_];   // [k][j]
__device__ __align__(16) float g_W3T[H_ * H_];   // [k][j]

// ---- packed f32x2 helpers (Blackwell) ----
__device__ __forceinline__ unsigned long long pk2(float lo, float hi) {
    unsigned long long r;
    asm("mov.b64 %0, {%1, %2};" : "=l"(r) : "f"(lo), "f"(hi));
    return r;
}
__device__ __forceinline__ void upk2(unsigned long long v, float& lo, float& hi) {
    asm("mov.b64 {%0, %1}, %2;" : "=f"(lo), "=f"(hi) : "l"(v));
}
__device__ __forceinline__ void addx2(unsigned long long& a, unsigned long long b) {
    asm("add.rn.f32x2 %0, %1, %2;" : "=l"(a) : "l"(a), "l"(b));
}

// per-row-group barrier (64 threads, ids 1..RPB)
#define BARG() asm volatile("bar.sync %0, 64;" :: "r"(barid) : "memory")

// ============================================================
// Tiled transpose of W1/W2/W3 into device globals.
// ============================================================
__global__ void __launch_bounds__(256) transpose_all(
    const float* __restrict__ W1, const float* __restrict__ W2,
    const float* __restrict__ W3) {
    __shared__ float tile[32][33];
    const int zi = blockIdx.z;
    const float* src = (zi == 0) ? W1 : ((zi == 1) ? W2 : W3);
    float* dst = (zi == 0) ? g_W1T : ((zi == 1) ? g_W2T : g_W3T);
    const int C = (zi == 0) ? F_ : H_;
    const int R = H_;
    if ((int)(blockIdx.x * 32) >= C) return;

    const int x = blockIdx.x * 32 + threadIdx.x;
    const int y0 = blockIdx.y * 32;
#pragma unroll
    for (int dy = threadIdx.y; dy < 32; dy += 8)
        tile[dy][threadIdx.x] = src[(size_t)(y0 + dy) * C + x];
    __syncthreads();
    const int x2 = y0 + threadIdx.x;
#pragma unroll
    for (int dy = threadIdx.y; dy < 32; dy += 8)
        dst[(size_t)(blockIdx.x * 32 + dy) * R + x2] = tile[threadIdx.x][dy];
}

// ============================================================
// gather over prescaled byte offsets, 4 accumulator chains, unroll 4
// (PROVEN codegen — do not restructure)
// ============================================================
__device__ __forceinline__ void gatherN(const char* __restrict__ wb,
                                        const uint32_t* __restrict__ lst, int n,
                                        unsigned long long& a01, unsigned long long& a23,
                                        unsigned long long& b01, unsigned long long& b23) {
    int e = 0;
    for (; e + 4 <= n; e += 4) {
        uint4 o = *(const uint4*)(lst + e);
        ulonglong2 w0 = *(const ulonglong2*)(wb + o.x);
        ulonglong2 w1 = *(const ulonglong2*)(wb + o.y);
        ulonglong2 w2 = *(const ulonglong2*)(wb + o.z);
        ulonglong2 w3 = *(const ulonglong2*)(wb + o.w);
        addx2(a01, w0.x); addx2(a23, w0.y);
        addx2(b01, w1.x); addx2(b23, w1.y);
        addx2(a01, w2.x); addx2(a23, w2.y);
        addx2(b01, w3.x); addx2(b23, w3.y);
    }
    for (; e < n; e++) {
        ulonglong2 w = *(const ulonglong2*)(wb + lst[e]);
        addx2(a01, w.x); addx2(a23, w.y);
    }
}

// ============================================================
// Main fused kernel (R15 structure) with SINGLE-DRAIN phase B:
// all three gather loops (W1[enc], fused W2/W3[z1] dual, W3[z2])
// issue back-to-back into disjoint accumulators; every merge /
// unpack / i-update is deferred to the end of the phase, so later
// loops' loads fill earlier loops' L2-latency tails (in-order issue).
// Merge order identical to R15 -> bit-exact output.
// ============================================================
__global__ void __launch_bounds__(256, 4)
snn_kernel(const float* __restrict__ x,
           const float* __restrict__ b1, const float* __restrict__ b2,
           const float* __restrict__ b3, const float* __restrict__ Wli,
           float* __restrict__ out) {
    __shared__ uint32_t s_bits[RPB][T_][32];                 // 12 KB
    __shared__ __align__(16) uint32_t s_le[RPB][512];        // 8 KB (enc offset list)
    __shared__ __align__(16) uint32_t s_lz[RPB][2 * H_];     // 8 KB (z1 @[0,H), z2 @[H,2H))
    __shared__ __align__(16) float    s_ex[RPB][EMAX];       // 8 KB (spiking x values)
    __shared__ uint16_t s_ef[RPB][EMAX];                     // 4 KB (their feature idx)
    __shared__ int s_ecnt[RPB];
    __shared__ int s_cntE[2][RPB];
    __shared__ int s_cnt1[2][RPB];
    __shared__ int s_cnt2[2][RPB];
    __shared__ float s_part[RPB][2][C_];

    const int tid = threadIdx.x;
    const int r = tid >> 6;
    const int g = tid & 63;
    const int lane = tid & 31;
    const int j0 = g * 4;
    const int barid = r + 1;
    const int row = blockIdx.x * RPB + r;
    const float* xrow = x + (size_t)row * F_;

    // ---- zero this row's bitmaps & counters (both parities) ----
    for (int i = g; i < T_ * 32; i += 64) ((uint32_t*)s_bits[r])[i] = 0;
    if (g == 0) {
        s_ecnt[r] = 0;
        s_cntE[0][r] = 0; s_cntE[1][r] = 0;
        s_cnt1[0][r] = 0; s_cnt1[1][r] = 0;
        s_cnt2[0][r] = 0; s_cnt2[1][r] = 0;
    }
    BARG();

    // ---- encoder stage 1: compact spiking candidates (x >= 1.08) ----
    {
#pragma unroll
        for (int m = 0; m < 16; m++) {
            const int f = g + 64 * m;
            float xv = xrow[f];
            if (xv >= 1.08f) {
                int p = atomicAdd(&s_ecnt[r], 1);
                if (p < EMAX) { s_ex[r][p] = xv; s_ef[r][p] = (uint16_t)f; }
            }
        }
    }
    BARG();

    // ---- encoder stage 2: exact 24-step fp32 LIF on compacted list ----
    {
        const int ne = s_ecnt[r];
        for (int i = g; i < ne; i += 64) {
            const float xv = s_ex[r][i];
            const int f = s_ef[r][i];
            const uint32_t bit = 1u << (f & 31);
            const int w = f >> 5;
            float v = 0.0f;
#pragma unroll
            for (int t = 0; t < T_; t++) {
                v = v + 0.1f * (xv - v);
                if (v > 1.0f) { atomicOr(&s_bits[r][t][w], bit); v = 0.0f; }
            }
        }
    }
    BARG();

    const char* W1b = (const char*)g_W1T + (size_t)j0 * 4;
    const char* W2b = (const char*)g_W2T + (size_t)j0 * 4;
    const char* W3b = (const char*)g_W3T + (size_t)j0 * 4;

    float v1[4] = {0,0,0,0}, i1[4] = {0,0,0,0};
    float v2[4] = {0,0,0,0}, i2[4] = {0,0,0,0};
    float v3[4] = {0,0,0,0}, i3[4] = {0,0,0,0};
    float q[4]  = {0,0,0,0};

    // readout coefficients: coef_t = 0.9^(23-t) - 0.8^(23-t)
    float c9 = 1.0f, c8 = 1.0f;
#pragma unroll
    for (int i = 0; i < T_ - 1; i++) { c9 *= 0.9f; c8 *= 0.8f; }

#pragma unroll 1
    for (int t = 0; t < T2; t++) {
        const int p = t & 1;

        // ===== phase A (pure ALU): step-t spikes from old state =====
        {
            if (g == 0) {   // opposite parity: last read in B(t-1), barrier-separated
                s_cntE[p ^ 1][r] = 0;
                s_cnt1[p ^ 1][r] = 0;
                s_cnt2[p ^ 1][r] = 0;
            }
            int* c1 = &s_cnt1[p][r];
            int* c2 = &s_cnt2[p][r];
            uint32_t* l1 = s_lz[r];
            uint32_t* l2 = s_lz[r] + H_;
            float coef = c9 - c8;
            c9 *= (1.0f / 0.9f);
            c8 *= 1.25f;
#pragma unroll
            for (int u = 0; u < 4; u++) {
                float vd1 = v1[u] + 0.1f * (i1[u] - v1[u]);
                bool z1 = vd1 > 0.23f;
                v1[u] = z1 ? 0.0f : vd1;
                float vd2 = v2[u] + 0.1f * (i2[u] - v2[u]);
                bool z2 = vd2 > 0.23f;
                v2[u] = z2 ? 0.0f : vd2;
                float vd3 = v3[u] + 0.1f * (i3[u] - v3[u]);
                bool z3 = vd3 > 0.23f;
                v3[u] = z3 ? 0.0f : vd3;
                if (z1) { int pp = atomicAdd(c1, 1); l1[pp] = (uint32_t)((j0 + u) << 10); }
                if (z2) { int pp = atomicAdd(c2, 1); l2[pp] = (uint32_t)((j0 + u) << 10); }
                float o3 = (z1 ? 1.0f : 0.0f) + (z2 ? 1.0f : 0.0f) + (z3 ? 1.0f : 0.0f);
                q[u] = fmaf(coef, o3, q[u]);
            }
            // build enc list for step t: 16-bit halves split over all 64 threads
            {
                const int word = g >> 1;
                const int sh = (g & 1) << 4;
                uint32_t bits = (s_bits[r][t][word] >> sh) & 0xFFFFu;
                const int base = (word << 5) + sh;
                while (bits) {
                    int b = __ffs(bits) - 1; bits &= bits - 1;
                    int pp = atomicAdd(&s_cntE[p][r], 1);
                    s_le[r][pp] = (uint32_t)((base + b) << 10);
                }
            }
        }
        BARG();

        // ===== phase B (pure memory): three loops back-to-back,
        //       ALL merges / unpacks / i-updates deferred to the end =====
        {
            // --- loop 1: W1[enc_t] into w-chains ---
            float4 bv1 = *(const float4*)(b1 + j0);
            unsigned long long w01 = pk2(bv1.x, bv1.y), w23 = pk2(bv1.z, bv1.w);
            unsigned long long w45 = pk2(0.f, 0.f),     w67 = pk2(0.f, 0.f);
            gatherN(W1b, s_le[r], s_cntE[p][r], w01, w23, w45, w67);

            // --- loop 2: fused dual over z1: W2 -> a-chains, W3 -> c-chains ---
            float4 bv2 = *(const float4*)(b2 + j0);
            float4 bv3 = *(const float4*)(b3 + j0);
            unsigned long long a01 = pk2(bv2.x, bv2.y), a23 = pk2(bv2.z, bv2.w);
            unsigned long long c01 = pk2(bv3.x, bv3.y), c23 = pk2(bv3.z, bv3.w);
            {
                const uint32_t* lz = s_lz[r];
                const int n1 = s_cnt1[p][r];
                int e = 0;
                for (; e + 2 <= n1; e += 2) {
                    uint2 o = *(const uint2*)(lz + e);
                    ulonglong2 wa0 = *(const ulonglong2*)(W2b + o.x);
                    ulonglong2 wc0 = *(const ulonglong2*)(W3b + o.x);
                    ulonglong2 wa1 = *(const ulonglong2*)(W2b + o.y);
                    ulonglong2 wc1 = *(const ulonglong2*)(W3b + o.y);
                    addx2(a01, wa0.x); addx2(a23, wa0.y);
                    addx2(c01, wc0.x); addx2(c23, wc0.y);
                    addx2(a01, wa1.x); addx2(a23, wa1.y);
                    addx2(c01, wc1.x); addx2(c23, wc1.y);
                }
                if (e < n1) {
                    uint32_t o = lz[e];
                    ulonglong2 wa = *(const ulonglong2*)(W2b + o);
                    ulonglong2 wc = *(const ulonglong2*)(W3b + o);
                    addx2(a01, wa.x); addx2(a23, wa.y);
                    addx2(c01, wc.x); addx2(c23, wc.y);
                }
            }

            // --- loop 3: W3[z2_t] into fresh d/e-chains ---
            unsigned long long d01 = pk2(0.f, 0.f), d23 = pk2(0.f, 0.f);
            unsigned long long e01 = pk2(0.f, 0.f), e23 = pk2(0.f, 0.f);
            gatherN(W3b, s_lz[r] + H_, s_cnt2[p][r], d01, d23, e01, e23);

            // --- single drain region: merges in R15 order, then updates ---
            addx2(w01, w45); addx2(w23, w67);         // W1 chains
            addx2(d01, e01); addx2(d23, e23);         // z2 chains
            addx2(c01, d01); addx2(c23, d23);         // fold z2 into W3
            float aw[4]; upk2(w01, aw[0], aw[1]); upk2(w23, aw[2], aw[3]);
            float a[4];  upk2(a01, a[0], a[1]);   upk2(a23, a[2], a[3]);
            float c[4];  upk2(c01, c[0], c[1]);   upk2(c23, c[2], c[3]);
#pragma unroll
            for (int u = 0; u < 4; u++) {
                i1[u] = i1[u] * 0.8f + aw[u];
                i2[u] = i2[u] * 0.8f + a[u];
                i3[u] = i3[u] * 0.8f + c[u];
            }
        }
        BARG();
    }

    // ===== step 22 epilogue: gathers dead; spikes from local state only =====
    {
        float coef = c9 - c8;   // = 0.9 - 0.8 = 0.1
#pragma unroll
        for (int u = 0; u < 4; u++) {
            float vd1 = v1[u] + 0.1f * (i1[u] - v1[u]);
            float vd2 = v2[u] + 0.1f * (i2[u] - v2[u]);
            float vd3 = v3[u] + 0.1f * (i3[u] - v3[u]);
            float o3 = (vd1 > 0.23f ? 1.0f : 0.0f)
                     + (vd2 > 0.23f ? 1.0f : 0.0f)
                     + (vd3 > 0.23f ? 1.0f : 0.0f);
            q[u] = fmaf(coef, o3, q[u]);
        }
    }
    // step 23: output coefficient is exactly 0 -> nothing to do.

    // ---- final readout: out[b][c] = sum_k q_k * Wli[c][k] ----
    const int wig = (tid >> 5) & 1;
#pragma unroll
    for (int c = 0; c < C_; c++) {
        float4 w = *(const float4*)(Wli + c * H_ + j0);
        float s = q[0] * w.x + q[1] * w.y + q[2] * w.z + q[3] * w.w;
#pragma unroll
        for (int off = 16; off; off >>= 1)
            s += __shfl_xor_sync(0xffffffffu, s, off);
        if (lane == 0) s_part[r][wig][c] = s;
    }
    BARG();
    if (g < C_) out[(size_t)row * C_ + g] = s_part[r][0][g] + s_part[r][1][g];
}

// ============================================================
extern "C" void kernel_launch(void* const* d_in, const int* in_sizes, int n_in,
                              void* d_out, int out_size) {
    (void)in_sizes; (void)n_in; (void)out_size;
    const float* x   = (const float*)d_in[0];
    const float* W1  = (const float*)d_in[1];
    const float* b1  = (const float*)d_in[2];
    const float* W2  = (const float*)d_in[3];
    const float* b2  = (const float*)d_in[4];
    const float* W3  = (const float*)d_in[5];
    const float* b3  = (const float*)d_in[6];
    const float* Wli = (const float*)d_in[7];
    float* out = (float*)d_out;

    transpose_all<<<dim3(F_ / 32, H_ / 32, 3), dim3(32, 8)>>>(W1, W2, W3);
    snn_kernel<<<B_ / RPB, 256>>>(x, b1, b2, b3, Wli, out);
}

// round 17
// speedup vs baseline: 1.7520x; 1.7520x over previous
#include <cuda_runtime.h>
#include <stdint.h>

#define B_   4096
#define F_   1024
#define H_   256
#define C_   10
#define T_   24
#define T2   (T_ - 2)     // steps 22/23 gathers are dead
#define RPB  2            // rows per CTA
#define TPR  128          // threads per row
#define EMAX 512

typedef unsigned long long ull;

// ---- transposed weights (device globals; no allocation) ----
__device__ __align__(16) float g_W1T[F_ * H_];   // [f][j]
__device__ __align__(16) float g_W2T[H_ * H_];   // [k][j]
__device__ __align__(16) float g_W3T[H_ * H_];   // [k][j]

// ---- packed f32x2 helpers (Blackwell) ----
__device__ __forceinline__ ull pk2(float lo, float hi) {
    ull r;
    asm("mov.b64 %0, {%1, %2};" : "=l"(r) : "f"(lo), "f"(hi));
    return r;
}
__device__ __forceinline__ void upk2(ull v, float& lo, float& hi) {
    asm("mov.b64 {%0, %1}, %2;" : "=f"(lo), "=f"(hi) : "l"(v));
}
__device__ __forceinline__ void addx2(ull& a, ull b) {
    asm("add.rn.f32x2 %0, %1, %2;" : "=l"(a) : "l"(a), "l"(b));
}

// per-row-group barrier (128 threads, ids 1..RPB)
#define BARG() asm volatile("bar.sync %0, 128;" :: "r"(barid) : "memory")

// ============================================================
// Tiled transpose of W1/W2/W3 into device globals.
// ============================================================
__global__ void __launch_bounds__(256) transpose_all(
    const float* __restrict__ W1, const float* __restrict__ W2,
    const float* __restrict__ W3) {
    __shared__ float tile[32][33];
    const int zi = blockIdx.z;
    const float* src = (zi == 0) ? W1 : ((zi == 1) ? W2 : W3);
    float* dst = (zi == 0) ? g_W1T : ((zi == 1) ? g_W2T : g_W3T);
    const int C = (zi == 0) ? F_ : H_;
    const int R = H_;
    if ((int)(blockIdx.x * 32) >= C) return;

    const int x = blockIdx.x * 32 + threadIdx.x;
    const int y0 = blockIdx.y * 32;
#pragma unroll
    for (int dy = threadIdx.y; dy < 32; dy += 8)
        tile[dy][threadIdx.x] = src[(size_t)(y0 + dy) * C + x];
    __syncthreads();
    const int x2 = y0 + threadIdx.x;
#pragma unroll
    for (int dy = threadIdx.y; dy < 32; dy += 8)
        dst[(size_t)(blockIdx.x * 32 + dy) * R + x2] = tile[threadIdx.x][dy];
}

// ============================================================
// 8B-per-thread gather, unroll 8, 4 chains: 8 loads in flight.
// ============================================================
__device__ __forceinline__ void gather8(const char* __restrict__ wb,
                                        const uint32_t* __restrict__ lst, int n,
                                        ull& a0, ull& a1, ull& a2, ull& a3) {
    int e = 0;
    for (; e + 8 <= n; e += 8) {
        uint4 o0 = *(const uint4*)(lst + e);
        uint4 o1 = *(const uint4*)(lst + e + 4);
        ull w0 = *(const ull*)(wb + o0.x);
        ull w1 = *(const ull*)(wb + o0.y);
        ull w2 = *(const ull*)(wb + o0.z);
        ull w3 = *(const ull*)(wb + o0.w);
        ull w4 = *(const ull*)(wb + o1.x);
        ull w5 = *(const ull*)(wb + o1.y);
        ull w6 = *(const ull*)(wb + o1.z);
        ull w7 = *(const ull*)(wb + o1.w);
        addx2(a0, w0); addx2(a1, w1); addx2(a2, w2); addx2(a3, w3);
        addx2(a0, w4); addx2(a1, w5); addx2(a2, w6); addx2(a3, w7);
    }
    for (; e < n; e++) {
        ull w = *(const ull*)(wb + lst[e]);
        addx2(a0, w);
    }
}

// ============================================================
// Main fused kernel: R15 champion structure transposed to
// 128 threads/row, 2 units/thread, 8B loads, unroll-8 -> 2x MLP.
//  A (pure ALU): z1/z2/z3 from old state; z-lists; q fold; enc list.
//  B (pure memory): W1[enc] gather; fused W2/W3 dual over z1;
//    W3[z2] gather. Dead steps 22/23 elided.
// ============================================================
__global__ void __launch_bounds__(256, 4)
snn_kernel(const float* __restrict__ x,
           const float* __restrict__ b1, const float* __restrict__ b2,
           const float* __restrict__ b3, const float* __restrict__ Wli,
           float* __restrict__ out) {
    __shared__ uint32_t s_bits[RPB][T_][32];                 // 6 KB
    __shared__ __align__(16) uint32_t s_le[RPB][512];        // 4 KB (enc offset list)
    __shared__ __align__(16) uint32_t s_lz[RPB][2 * H_];     // 4 KB (z1 @[0,H), z2 @[H,2H))
    __shared__ __align__(16) float    s_ex[RPB][EMAX];       // 4 KB
    __shared__ uint16_t s_ef[RPB][EMAX];                     // 2 KB
    __shared__ int s_ecnt[RPB];
    __shared__ int s_cntE[2][RPB];
    __shared__ int s_cnt1[2][RPB];
    __shared__ int s_cnt2[2][RPB];
    __shared__ float s_part[RPB][4][C_];

    const int tid = threadIdx.x;
    const int r = tid >> 7;
    const int g = tid & 127;
    const int lane = tid & 31;
    const int j0 = g * 2;              // 2 hidden units per thread
    const int barid = r + 1;
    const int row = blockIdx.x * RPB + r;
    const float* xrow = x + (size_t)row * F_;

    // ---- zero this row's bitmaps & counters ----
    for (int i = g; i < T_ * 32; i += TPR) ((uint32_t*)s_bits[r])[i] = 0;
    if (g == 0) {
        s_ecnt[r] = 0;
        s_cntE[0][r] = 0; s_cntE[1][r] = 0;
        s_cnt1[0][r] = 0; s_cnt1[1][r] = 0;
        s_cnt2[0][r] = 0; s_cnt2[1][r] = 0;
    }
    BARG();

    // ---- encoder stage 1: compact spiking candidates (x >= 1.08) ----
    {
#pragma unroll
        for (int m = 0; m < 8; m++) {
            const int f = g + TPR * m;
            float xv = xrow[f];
            if (xv >= 1.08f) {
                int p = atomicAdd(&s_ecnt[r], 1);
                if (p < EMAX) { s_ex[r][p] = xv; s_ef[r][p] = (uint16_t)f; }
            }
        }
    }
    BARG();

    // ---- encoder stage 2: exact 24-step fp32 LIF on compacted list ----
    {
        const int ne = s_ecnt[r];
        for (int i = g; i < ne; i += TPR) {
            const float xv = s_ex[r][i];
            const int f = s_ef[r][i];
            const uint32_t bit = 1u << (f & 31);
            const int w = f >> 5;
            float v = 0.0f;
#pragma unroll
            for (int t = 0; t < T_; t++) {
                v = v + 0.1f * (xv - v);
                if (v > 1.0f) { atomicOr(&s_bits[r][t][w], bit); v = 0.0f; }
            }
        }
    }
    BARG();

    const char* W1b = (const char*)g_W1T + (size_t)j0 * 4;
    const char* W2b = (const char*)g_W2T + (size_t)j0 * 4;
    const char* W3b = (const char*)g_W3T + (size_t)j0 * 4;

    float v1[2] = {0,0}, i1[2] = {0,0};
    float v2[2] = {0,0}, i2[2] = {0,0};
    float v3[2] = {0,0}, i3[2] = {0,0};
    float q[2]  = {0,0};

    // readout coefficients: coef_t = 0.9^(23-t) - 0.8^(23-t)
    float c9 = 1.0f, c8 = 1.0f;
#pragma unroll
    for (int i = 0; i < T_ - 1; i++) { c9 *= 0.9f; c8 *= 0.8f; }

#pragma unroll 1
    for (int t = 0; t < T2; t++) {
        const int p = t & 1;

        // ===== phase A (pure ALU): step-t spikes from old state =====
        {
            if (g == 0) {
                s_cntE[p ^ 1][r] = 0;
                s_cnt1[p ^ 1][r] = 0;
                s_cnt2[p ^ 1][r] = 0;
            }
            int* c1 = &s_cnt1[p][r];
            int* c2 = &s_cnt2[p][r];
            uint32_t* l1 = s_lz[r];
            uint32_t* l2 = s_lz[r] + H_;
            float coef = c9 - c8;
            c9 *= (1.0f / 0.9f);
            c8 *= 1.25f;
#pragma unroll
            for (int u = 0; u < 2; u++) {
                float vd1 = v1[u] + 0.1f * (i1[u] - v1[u]);
                bool z1 = vd1 > 0.23f;
                v1[u] = z1 ? 0.0f : vd1;
                float vd2 = v2[u] + 0.1f * (i2[u] - v2[u]);
                bool z2 = vd2 > 0.23f;
                v2[u] = z2 ? 0.0f : vd2;
                float vd3 = v3[u] + 0.1f * (i3[u] - v3[u]);
                bool z3 = vd3 > 0.23f;
                v3[u] = z3 ? 0.0f : vd3;
                if (z1) { int pp = atomicAdd(c1, 1); l1[pp] = (uint32_t)((j0 + u) << 10); }
                if (z2) { int pp = atomicAdd(c2, 1); l2[pp] = (uint32_t)((j0 + u) << 10); }
                float o3 = (z1 ? 1.0f : 0.0f) + (z2 ? 1.0f : 0.0f) + (z3 ? 1.0f : 0.0f);
                q[u] = fmaf(coef, o3, q[u]);
            }
            // build enc list for step t: 8-bit slices over 128 threads
            {
                const int word = g >> 2;
                const int sh = (g & 3) << 3;
                uint32_t bits = (s_bits[r][t][word] >> sh) & 0xFFu;
                const int base = (word << 5) + sh;
                while (bits) {
                    int b = __ffs(bits) - 1; bits &= bits - 1;
                    int pp = atomicAdd(&s_cntE[p][r], 1);
                    s_le[r][pp] = (uint32_t)((base + b) << 10);
                }
            }
        }
        BARG();

        // ===== phase B (pure memory): gathers back-to-back =====
        {
            // W1[enc_t] -> i1 (unroll-8, 8 loads in flight)
            {
                float2 bv = *(const float2*)(b1 + j0);
                ull a0 = pk2(bv.x, bv.y);
                ull a1 = pk2(0.f, 0.f), a2 = pk2(0.f, 0.f), a3 = pk2(0.f, 0.f);
                gather8(W1b, s_le[r], s_cntE[p][r], a0, a1, a2, a3);
                addx2(a0, a1); addx2(a2, a3); addx2(a0, a2);
                float a[2]; upk2(a0, a[0], a[1]);
#pragma unroll
                for (int u = 0; u < 2; u++) i1[u] = i1[u] * 0.8f + a[u];
            }
            // FUSED dual loop over z1: W2 -> a-chains, W3 -> c-chains
            // (unroll 4 x 2 matrices = 8 loads in flight)
            {
                float2 bv2 = *(const float2*)(b2 + j0);
                float2 bv3 = *(const float2*)(b3 + j0);
                ull a0 = pk2(bv2.x, bv2.y), a1 = pk2(0.f, 0.f);
                ull c0 = pk2(bv3.x, bv3.y), c1 = pk2(0.f, 0.f);
                const uint32_t* lz = s_lz[r];
                const int n1 = s_cnt1[p][r];
                int e = 0;
                for (; e + 4 <= n1; e += 4) {
                    uint4 o = *(const uint4*)(lz + e);
                    ull pa0 = *(const ull*)(W2b + o.x);
                    ull qa0 = *(const ull*)(W3b + o.x);
                    ull pa1 = *(const ull*)(W2b + o.y);
                    ull qa1 = *(const ull*)(W3b + o.y);
                    ull pa2 = *(const ull*)(W2b + o.z);
                    ull qa2 = *(const ull*)(W3b + o.z);
                    ull pa3 = *(const ull*)(W2b + o.w);
                    ull qa3 = *(const ull*)(W3b + o.w);
                    addx2(a0, pa0); addx2(c0, qa0);
                    addx2(a1, pa1); addx2(c1, qa1);
                    addx2(a0, pa2); addx2(c0, qa2);
                    addx2(a1, pa3); addx2(c1, qa3);
                }
                for (; e < n1; e++) {
                    uint32_t o = lz[e];
                    ull pa = *(const ull*)(W2b + o);
                    ull qa = *(const ull*)(W3b + o);
                    addx2(a0, pa); addx2(c0, qa);
                }
                addx2(a0, a1);
                float a[2]; upk2(a0, a[0], a[1]);
#pragma unroll
                for (int u = 0; u < 2; u++) i2[u] = i2[u] * 0.8f + a[u];

                // W3[z2_t] into fresh chains, then fold into c
                {
                    ull d0 = pk2(0.f, 0.f), d1 = pk2(0.f, 0.f);
                    ull d2 = pk2(0.f, 0.f), d3 = pk2(0.f, 0.f);
                    gather8(W3b, s_lz[r] + H_, s_cnt2[p][r], d0, d1, d2, d3);
                    addx2(d0, d1); addx2(d2, d3); addx2(d0, d2);
                    addx2(c0, c1); addx2(c0, d0);
                }
                float c[2]; upk2(c0, c[0], c[1]);
#pragma unroll
                for (int u = 0; u < 2; u++) i3[u] = i3[u] * 0.8f + c[u];
            }
        }
        BARG();
    }

    // ===== step 22 epilogue: gathers dead; spikes from local state only =====
    {
        float coef = c9 - c8;   // = 0.1
#pragma unroll
        for (int u = 0; u < 2; u++) {
            float vd1 = v1[u] + 0.1f * (i1[u] - v1[u]);
            float vd2 = v2[u] + 0.1f * (i2[u] - v2[u]);
            float vd3 = v3[u] + 0.1f * (i3[u] - v3[u]);
            float o3 = (vd1 > 0.23f ? 1.0f : 0.0f)
                     + (vd2 > 0.23f ? 1.0f : 0.0f)
                     + (vd3 > 0.23f ? 1.0f : 0.0f);
            q[u] = fmaf(coef, o3, q[u]);
        }
    }
    // step 23: output coefficient is exactly 0 -> nothing to do.

    // ---- final readout: out[b][c] = sum_k q_k * Wli[c][k] ----
    const int wig = g >> 5;   // 0..3
#pragma unroll
    for (int c = 0; c < C_; c++) {
        float2 w = *(const float2*)(Wli + c * H_ + j0);
        float s = q[0] * w.x + q[1] * w.y;
#pragma unroll
        for (int off = 16; off; off >>= 1)
            s += __shfl_xor_sync(0xffffffffu, s, off);
        if (lane == 0) s_part[r][wig][c] = s;
    }
    BARG();
    if (g < C_)
        out[(size_t)row * C_ + g] = (s_part[r][0][g] + s_part[r][1][g])
                                  + (s_part[r][2][g] + s_part[r][3][g]);
}

// ============================================================
extern "C" void kernel_launch(void* const* d_in, const int* in_sizes, int n_in,
                              void* d_out, int out_size) {
    (void)in_sizes; (void)n_in; (void)out_size;
    const float* x   = (const float*)d_in[0];
    const float* W1  = (const float*)d_in[1];
    const float* b1  = (const float*)d_in[2];
    const float* W2  = (const float*)d_in[3];
    const float* b2  = (const float*)d_in[4];
    const float* W3  = (const float*)d_in[5];
    const float* b3  = (const float*)d_in[6];
    const float* Wli = (const float*)d_in[7];
    float* out = (float*)d_out;

    transpose_all<<<dim3(F_ / 32, H_ / 32, 3), dim3(32, 8)>>>(W1, W2, W3);
    snn_kernel<<<B_ / RPB, 256>>>(x, b1, b2, b3, Wli, out);
}